// round 16
// baseline (speedup 1.0000x reference)
#include <cuda_runtime.h>
#include <math.h>

#define BB 4
#define C 64
#define CQn 8
#define H 256
#define W 256
#define HW 65536
#define CHW (C*HW)          // 4194304
#define TOT (BB*CHW)        // 16777216

typedef unsigned long long u64;

// ---- packed f32x2 helpers ----
__device__ __forceinline__ u64 pk2(float a, float b) {
    u64 r;
    asm("mov.b64 %0, {%1, %2};" : "=l"(r) : "r"(__float_as_uint(a)), "r"(__float_as_uint(b)));
    return r;
}
__device__ __forceinline__ void upk2(u64 v, float& a, float& b) {
    unsigned lo, hi;
    asm("mov.b64 {%0, %1}, %2;" : "=r"(lo), "=r"(hi) : "l"(v));
    a = __uint_as_float(lo); b = __uint_as_float(hi);
}
__device__ __forceinline__ u64 fma2(u64 a, u64 b, u64 c) {
    u64 d;
    asm("fma.rn.f32x2 %0, %1, %2, %3;" : "=l"(d) : "l"(a), "l"(b), "l"(c));
    return d;
}
__device__ __forceinline__ u64 add2(u64 a, u64 b) {
    u64 d;
    asm("add.rn.f32x2 %0, %1, %2;" : "=l"(d) : "l"(a), "l"(b));
    return d;
}

// ---------------- scratch ----------------
__device__ float g_y0[TOT];                 // pre-norm pointwise output (NCHW)
__device__ float g_val[TOT];                // v projection (channels-last [b][h][w][c])
__device__ float g_att[TOT];                // h_out (channels-last [b][i][w][c])
__device__ float g_q[BB*HW*CQn];            // channels-last [b][h][w][8]
__device__ float g_k[BB*HW*CQn];
__device__ float g_isum[BB*C], g_isq[BB*C];
__device__ float g_alpha[BB*C], g_beta[BB*C];
__device__ float g_wT[BB*C*80];             // folded qkv weights [b][c][80]
__device__ float g_bf[BB*80];               // folded qkv biases  [b][80]

// ---------------- 0) zero the stat accumulators ----------------
__global__ void k_zero() {
    int t = threadIdx.x;
    if (t < BB*C) { g_isum[t] = 0.f; g_isq[t] = 0.f; }
}

// ---------------- 1) axial conv + relu + pointwise + fused instance stats ----------------
__global__ __launch_bounds__(256, 2)
void k_conv_pw(const float* __restrict__ x,
               const float* __restrict__ hw_, const float* __restrict__ hb,
               const float* __restrict__ vw_, const float* __restrict__ vb,
               const float* __restrict__ pww, const float* __restrict__ pwb) {
    extern __shared__ float s_stage[];      // 256 x 68
    __shared__ float s_hw[C*5], s_vw[C*5], s_hb[C], s_vb[C];
    __shared__ float s_pwT[C*C];            // [c][o] transposed
    __shared__ u64   s_pwb2[C/2];
    int tid = threadIdx.x;
    for (int i = tid; i < C*5; i += 256) { s_hw[i] = hw_[i]; s_vw[i] = vw_[i]; }
    for (int i = tid; i < C;   i += 256) { s_hb[i] = hb[i]; s_vb[i] = vb[i]; }
    for (int i = tid; i < C*C; i += 256) { int o = i >> 6, c = i & 63; s_pwT[c*C + o] = pww[i]; }
    if (tid < C/2) s_pwb2[tid] = pk2(pwb[2*tid], pwb[2*tid+1]);
    __syncthreads();

    int row = blockIdx.x;
    int b = row >> 8, h = row & 255;
    int w = tid;
    const float* xb = x + (size_t)b * CHW;

    u64 acc[C/2];
    #pragma unroll
    for (int o = 0; o < C/2; o++) acc[o] = s_pwb2[o];

    bool wok[5], hok[5];
    #pragma unroll
    for (int t = 0; t < 5; t++) {
        int ww = w + t - 2; wok[t] = (ww >= 0 && ww < W);
        int hh = h + t - 2; hok[t] = (hh >= 0 && hh < H);
    }

    float xh_a[5], xv_a[5], xh_b[5], xv_b[5];
    {
        const float* xc = xb + h * W;
        #pragma unroll
        for (int t = 0; t < 5; t++) {
            xh_a[t] = wok[t] ? xc[w + t - 2] : 0.f;
            xv_a[t] = hok[t] ? xb[(h + t - 2)*W + w] : 0.f;
        }
    }
    #pragma unroll 4
    for (int c = 0; c < C; c++) {
        float* xh = (c & 1) ? xh_b : xh_a;
        float* xv = (c & 1) ? xv_b : xv_a;
        float* nh = (c & 1) ? xh_a : xh_b;
        float* nv = (c & 1) ? xv_a : xv_b;
        if (c < C-1) {
            const float* xc1 = xb + (c+1) * HW + h * W;
            #pragma unroll
            for (int t = 0; t < 5; t++) {
                nh[t] = wok[t] ? xc1[w + t - 2] : 0.f;
                nv[t] = hok[t] ? xb[(c+1)*HW + (h + t - 2)*W + w] : 0.f;
            }
        }
        float hs = s_hb[c], vs = s_vb[c];
        #pragma unroll
        for (int t = 0; t < 5; t++) {
            hs = fmaf(s_hw[c*5 + t], xh[t], hs);
            vs = fmaf(s_vw[c*5 + t], xv[t], vs);
        }
        float a = hs + vs + xh[2];
        a = a > 0.f ? a : 0.f;
        u64 a2 = pk2(a, a);
        const ulonglong2* wr = (const ulonglong2*)(s_pwT + c*C);
        #pragma unroll
        for (int o = 0; o < C/4; o++) {
            ulonglong2 ww = wr[o];
            acc[2*o]   = fma2(a2, ww.x, acc[2*o]);
            acc[2*o+1] = fma2(a2, ww.y, acc[2*o+1]);
        }
    }
    size_t base = (size_t)b * CHW + h * W + w;
    #pragma unroll
    for (int o = 0; o < C/2; o++) {
        float a, bb; upk2(acc[o], a, bb);
        g_y0[base + (size_t)(2*o)   * HW] = a;
        g_y0[base + (size_t)(2*o+1) * HW] = bb;
        s_stage[tid*68 + 2*o]     = a;
        s_stage[tid*68 + 2*o + 1] = bb;
    }
    __syncthreads();
    {
        int ch = tid & 63, pb = tid >> 6;
        float s = 0.f, qq = 0.f;
        #pragma unroll 8
        for (int p = pb*64; p < pb*64 + 64; p++) {
            float v = s_stage[p*68 + ch];
            s += v; qq = fmaf(v, v, qq);
        }
        atomicAdd(&g_isum[b*C + ch], s);
        atomicAdd(&g_isq [b*C + ch], qq);
    }
}

// ---------------- 3) alpha/beta + folded qkv weights/biases ----------------
__global__ __launch_bounds__(256)
void k_prep(const float* __restrict__ bn_w, const float* __restrict__ bn_b,
            const float* __restrict__ qw, const float* __restrict__ qb,
            const float* __restrict__ kw, const float* __restrict__ kb,
            const float* __restrict__ vw, const float* __restrict__ vb) {
    __shared__ float s_al[BB*C], s_be[BB*C];
    int tid = threadIdx.x;
    if (tid < C) {
        int c = tid;
        const float EPS = 1e-5f, R = 0.7f, R1 = 0.3f;
        float im[BB], iv[BB];
        float bm = 0.f, ey2 = 0.f;
        for (int b = 0; b < BB; b++) {
            float s  = g_isum[b*C + c] * (1.0f/HW);
            float sq = g_isq [b*C + c] * (1.0f/HW);
            im[b] = s; iv[b] = sq - s*s;
            bm += s; ey2 += sq;
        }
        bm *= 0.25f; ey2 *= 0.25f;
        float bv = ey2 - bm*bm;
        float rB = rsqrtf(bv + EPS);
        float wv = bn_w[c], bb = bn_b[c];
        for (int b = 0; b < BB; b++) {
            float rI = rsqrtf(iv[b] + EPS);
            float al = R*rI + R1*rB*wv;
            float be = -R*im[b]*rI + R1*(bb - bm*rB*wv);
            g_alpha[b*C + c] = al; g_beta[b*C + c] = be;
            s_al[b*C + c] = al;    s_be[b*C + c] = be;
        }
    }
    __syncthreads();
    for (int idx = tid; idx < BB*C*80; idx += 256) {
        int b = idx / (C*80);
        int r = idx % (C*80);
        int c = r / 80, o = r % 80;
        float wv = (o < 8) ? qw[o*C + c] : (o < 16) ? kw[(o-8)*C + c] : vw[(o-16)*C + c];
        g_wT[idx] = wv * s_al[b*C + c];
    }
    for (int t = tid; t < BB*80; t += 256) {
        int b = t / 80, o = t % 80;
        float s = (o < 8) ? qb[o] : (o < 16) ? kb[o-8] : vb[o-16];
        const float* wrow = (o < 8) ? (qw + o*C) : (o < 16) ? (kw + (o-8)*C) : (vw + (o-16)*C);
        #pragma unroll 8
        for (int c = 0; c < C; c++) s = fmaf(wrow[c], s_be[b*C + c], s);
        g_bf[t] = s;
    }
}

// ---------------- 4) q/k/v projections: o-split + 2 px/thread ----------------
// Thread t: ho = t>>7 (output half: o in [ho*40, ho*40+40)), qi = t&127,
// pixels 2*qi and 2*qi+1 of row h. Each weight LDS.128 feeds 4 FFMA2.
__global__ __launch_bounds__(256, 2)
void k_qkv() {
    extern __shared__ float sm[];
    float* s_wT    = sm;                    // 64 x 80 (folded, this batch)
    float* s_stage = sm + C*80;             // 256 x 68 (padded)
    __shared__ u64 s_b2[40];
    int tid = threadIdx.x;
    int b = blockIdx.x >> 8, h = blockIdx.x & 255;
    int ho = tid >> 7;                      // 0 or 1
    int qi = tid & 127;
    int px = 2 * qi;

    for (int i = tid; i < C*80; i += 256) s_wT[i] = g_wT[b*C*80 + i];
    if (tid < 40) s_b2[tid] = pk2(g_bf[b*80 + 2*tid], g_bf[b*80 + 2*tid + 1]);
    __syncthreads();

    u64 acc0[20], acc1[20];                 // px, px+1 : 20 o-pairs each
    #pragma unroll
    for (int u = 0; u < 20; u++) { acc0[u] = s_b2[ho*20 + u]; acc1[u] = s_b2[ho*20 + u]; }

    size_t ybase = (size_t)b * CHW + h * W + px;
    const int ho40 = ho * 40;
    float2 ya[8], yb[8];
    #pragma unroll
    for (int u = 0; u < 8; u++) ya[u] = *(const float2*)(g_y0 + ybase + (size_t)u * HW);
    #pragma unroll
    for (int cb = 0; cb < 8; cb++) {
        float2* ycur = (cb & 1) ? yb : ya;
        float2* ynxt = (cb & 1) ? ya : yb;
        if (cb < 7) {
            #pragma unroll
            for (int u = 0; u < 8; u++)
                ynxt[u] = *(const float2*)(g_y0 + ybase + (size_t)(8*(cb+1) + u) * HW);
        }
        #pragma unroll
        for (int u = 0; u < 8; u++) {
            int c = cb*8 + u;
            u64 yA = pk2(ycur[u].x, ycur[u].x);
            u64 yB = pk2(ycur[u].y, ycur[u].y);
            const ulonglong2* wr = (const ulonglong2*)(s_wT + c*80 + ho40);
            #pragma unroll
            for (int o = 0; o < 10; o++) {
                ulonglong2 ww = wr[o];
                acc0[2*o]   = fma2(yA, ww.x, acc0[2*o]);
                acc0[2*o+1] = fma2(yA, ww.y, acc0[2*o+1]);
                acc1[2*o]   = fma2(yB, ww.x, acc1[2*o]);
                acc1[2*o+1] = fma2(yB, ww.y, acc1[2*o+1]);
            }
        }
    }

    if (ho == 0) {
        // o 0-7 = q, 8-15 = k : per-pixel float4 writes (channels-last)
        size_t pq = ((size_t)b*HW + h*W + px) * 8;
        float a0,a1,a2,a3;
        upk2(acc0[0], a0, a1); upk2(acc0[1], a2, a3);
        *(float4*)(g_q + pq) = make_float4(a0,a1,a2,a3);
        upk2(acc0[2], a0, a1); upk2(acc0[3], a2, a3);
        *(float4*)(g_q + pq + 4) = make_float4(a0,a1,a2,a3);
        upk2(acc0[4], a0, a1); upk2(acc0[5], a2, a3);
        *(float4*)(g_k + pq) = make_float4(a0,a1,a2,a3);
        upk2(acc0[6], a0, a1); upk2(acc0[7], a2, a3);
        *(float4*)(g_k + pq + 4) = make_float4(a0,a1,a2,a3);
        upk2(acc1[0], a0, a1); upk2(acc1[1], a2, a3);
        *(float4*)(g_q + pq + 8) = make_float4(a0,a1,a2,a3);
        upk2(acc1[2], a0, a1); upk2(acc1[3], a2, a3);
        *(float4*)(g_q + pq + 12) = make_float4(a0,a1,a2,a3);
        upk2(acc1[4], a0, a1); upk2(acc1[5], a2, a3);
        *(float4*)(g_k + pq + 8) = make_float4(a0,a1,a2,a3);
        upk2(acc1[6], a0, a1); upk2(acc1[7], a2, a3);
        *(float4*)(g_k + pq + 12) = make_float4(a0,a1,a2,a3);
        // v channels 0-23 (o 16-39 -> pairs 8-19)
        #pragma unroll
        for (int u = 8; u < 20; u++) {
            int c0 = 2*u - 16;
            float a, bb;
            upk2(acc0[u], a, bb);
            s_stage[px*68 + c0] = a; s_stage[px*68 + c0 + 1] = bb;
            upk2(acc1[u], a, bb);
            s_stage[(px+1)*68 + c0] = a; s_stage[(px+1)*68 + c0 + 1] = bb;
        }
    } else {
        // v channels 24-63 (o 40-79 -> pairs 0-19)
        #pragma unroll
        for (int u = 0; u < 20; u++) {
            int c0 = 24 + 2*u;
            float a, bb;
            upk2(acc0[u], a, bb);
            s_stage[px*68 + c0] = a; s_stage[px*68 + c0 + 1] = bb;
            upk2(acc1[u], a, bb);
            s_stage[(px+1)*68 + c0] = a; s_stage[(px+1)*68 + c0 + 1] = bb;
        }
    }
    __syncthreads();
    float4* gv = (float4*)(g_val + ((size_t)b*HW + h*W) * 64);
    for (int e = tid; e < 4096; e += 256) {
        int p = e >> 4, c4 = e & 15;
        gv[e] = *(float4*)(s_stage + p*68 + c4*4);
    }
}

// ---------------- 5) criss-cross attention: 128 threads, 2 pixels/thread ----------------
__global__ __launch_bounds__(128)
void k_attn(int height, float* __restrict__ out, const float* __restrict__ gamma) {
    extern __shared__ float sm[];
    float* q_s = sm;            // 256 x 8
    float* k_s = sm + 2048;     // 256 x 8
    float* z_s = sm + 4096;     // 256 (invz)
    float* v_s = sm + 4352;     // 256 x 68 (padded)
    int tid = threadIdx.x;
    int b = blockIdx.x >> 8;
    int f = blockIdx.x & 255;
    int p0 = tid, p1 = tid + 128;

    const float4* gq = (const float4*)(g_q   + (size_t)b*HW*8);
    const float4* gk = (const float4*)(g_k   + (size_t)b*HW*8);
    const float4* gv = (const float4*)(g_val + (size_t)b*HW*64);

    if (height) {
        for (int e = tid; e < 512; e += 128) {
            int j = e >> 1, c4 = e & 1;
            size_t g = ((size_t)j*W + f)*2 + c4;
            ((float4*)q_s)[e] = gq[g];
            ((float4*)k_s)[e] = gk[g];
        }
        for (int e = tid; e < 4096; e += 128) {
            int j = e >> 4, c4 = e & 15;
            *(float4*)(v_s + j*68 + c4*4) = gv[((size_t)j*W + f)*16 + c4];
        }
    } else {
        size_t pb = (size_t)f * W;
        for (int e = tid; e < 512; e += 128) {
            ((float4*)q_s)[e] = gq[pb*2 + e];
            ((float4*)k_s)[e] = gk[pb*2 + e];
        }
        for (int e = tid; e < 4096; e += 128) {
            int j = e >> 4, c4 = e & 15;
            *(float4*)(v_s + j*68 + c4*4) = gv[pb*16 + e];
        }
    }
    __syncthreads();

    const u64 zero2 = pk2(0.f, 0.f);

    u64 k0r[4], k1r[4];
    {
        const ulonglong2* kp0 = (const ulonglong2*)(k_s + p0*8);
        const ulonglong2* kp1 = (const ulonglong2*)(k_s + p1*8);
        ulonglong2 t;
        t = kp0[0]; k0r[0] = t.x; k0r[1] = t.y;
        t = kp0[1]; k0r[2] = t.x; k0r[3] = t.y;
        t = kp1[0]; k1r[0] = t.x; k1r[1] = t.y;
        t = kp1[1]; k1r[2] = t.x; k1r[3] = t.y;
    }

    // ---- pass 1 (thread = sources p0,p1): Z_j = sum_i exp(q_j . k_i) ----
    {
        u64 q0r[4], q1r[4];
        const ulonglong2* qp0 = (const ulonglong2*)(q_s + p0*8);
        const ulonglong2* qp1 = (const ulonglong2*)(q_s + p1*8);
        ulonglong2 t;
        t = qp0[0]; q0r[0] = t.x; q0r[1] = t.y;
        t = qp0[1]; q0r[2] = t.x; q0r[3] = t.y;
        t = qp1[0]; q1r[0] = t.x; q1r[1] = t.y;
        t = qp1[1]; q1r[2] = t.x; q1r[3] = t.y;
        float z0 = 0.f, z1 = 0.f;
        for (int i = 0; i < 256; i++) {
            const ulonglong2* kp = (const ulonglong2*)(k_s + i*8);   // broadcast
            ulonglong2 k01 = kp[0], k23 = kp[1];
            u64 a0 = fma2(q0r[1], k01.y, fma2(q0r[0], k01.x, zero2));
            u64 a1 = fma2(q0r[3], k23.y, fma2(q0r[2], k23.x, zero2));
            float sx, sy; upk2(add2(a0, a1), sx, sy);
            z0 += __expf(sx + sy);
            u64 b0 = fma2(q1r[1], k01.y, fma2(q1r[0], k01.x, zero2));
            u64 b1 = fma2(q1r[3], k23.y, fma2(q1r[2], k23.x, zero2));
            upk2(add2(b0, b1), sx, sy);
            z1 += __expf(sx + sy);
        }
        z_s[p0] = 1.0f / z0;
        z_s[p1] = 1.0f / z1;
    }
    __syncthreads();

    // ---- pass 2 (thread = outputs p0,p1) ----
    u64 acc0[32], acc1[32];
    #pragma unroll
    for (int u = 0; u < 32; u++) { acc0[u] = zero2; acc1[u] = zero2; }
    for (int j = 0; j < 256; j++) {
        const ulonglong2* qp = (const ulonglong2*)(q_s + j*8);       // broadcast
        ulonglong2 q01 = qp[0], q23 = qp[1];
        u64 a0 = fma2(k0r[1], q01.y, fma2(k0r[0], q01.x, zero2));
        u64 a1 = fma2(k0r[3], q23.y, fma2(k0r[2], q23.x, zero2));
        float sx, sy; upk2(add2(a0, a1), sx, sy);
        float izj = z_s[j];
        float e0 = __expf(sx + sy) * izj;
        u64 b0 = fma2(k1r[1], q01.y, fma2(k1r[0], q01.x, zero2));
        u64 b1 = fma2(k1r[3], q23.y, fma2(k1r[2], q23.x, zero2));
        upk2(add2(b0, b1), sx, sy);
        float e1 = __expf(sx + sy) * izj;
        u64 e02 = pk2(e0, e0), e12 = pk2(e1, e1);
        const ulonglong2* vr = (const ulonglong2*)(v_s + j*68);      // broadcast
        #pragma unroll
        for (int u = 0; u < 16; u++) {
            ulonglong2 vv = vr[u];
            acc0[2*u]   = fma2(e02, vv.x, acc0[2*u]);
            acc0[2*u+1] = fma2(e02, vv.y, acc0[2*u+1]);
            acc1[2*u]   = fma2(e12, vv.x, acc1[2*u]);
            acc1[2*u+1] = fma2(e12, vv.y, acc1[2*u+1]);
        }
    }

    if (height) {
        __syncthreads();
        #pragma unroll
        for (int u = 0; u < 32; u++) {
            float a, bb;
            upk2(acc0[u], a, bb);
            v_s[p0*68 + 2*u] = a; v_s[p0*68 + 2*u + 1] = bb;
            upk2(acc1[u], a, bb);
            v_s[p1*68 + 2*u] = a; v_s[p1*68 + 2*u + 1] = bb;
        }
        __syncthreads();
        float4* ga = (float4*)(g_att + (size_t)b*HW*64);
        for (int e = tid; e < 4096; e += 128) {
            int j = e >> 4, c4 = e & 15;
            ga[((size_t)j*W + f)*16 + c4] = *(float4*)(v_s + j*68 + c4*4);
        }
    } else {
        __syncthreads();
        u64* s_al2 = (u64*)q_s;           // 32 pairs
        u64* s_be2 = ((u64*)q_s) + 32;
        if (tid < 32) {
            s_al2[tid] = pk2(g_alpha[b*C + 2*tid], g_alpha[b*C + 2*tid + 1]);
            s_be2[tid] = pk2(g_beta [b*C + 2*tid], g_beta [b*C + 2*tid + 1]);
        }
        const float4* ga = (const float4*)(g_att + ((size_t)b*HW + (size_t)f*W) * 64);
        for (int e = tid; e < 4096; e += 128) {
            int p = e >> 4, c4 = e & 15;
            *(float4*)(v_s + p*68 + c4*4) = ga[e];
        }
        __syncthreads();
        float gm = gamma[0];
        u64 gm2 = pk2(gm, gm);
        size_t obase = (size_t)b*CHW + (size_t)f*W;
        const u64* ar0 = (const u64*)(v_s + p0*68);
        const u64* ar1 = (const u64*)(v_s + p1*68);
        #pragma unroll
        for (int u = 0; u < 32; u++) {
            u64 hv0 = add2(ar0[u], acc0[u]);
            u64 y20 = pk2(g_y0[obase + (size_t)(2*u)*HW + p0], g_y0[obase + (size_t)(2*u+1)*HW + p0]);
            u64 r0 = fma2(gm2, hv0, fma2(s_al2[u], y20, s_be2[u]));
            float ra, rb; upk2(r0, ra, rb);
            out[obase + (size_t)(2*u)  *HW + p0] = ra;
            out[obase + (size_t)(2*u+1)*HW + p0] = rb;
            u64 hv1 = add2(ar1[u], acc1[u]);
            u64 y21 = pk2(g_y0[obase + (size_t)(2*u)*HW + p1], g_y0[obase + (size_t)(2*u+1)*HW + p1]);
            u64 r1 = fma2(gm2, hv1, fma2(s_al2[u], y21, s_be2[u]));
            upk2(r1, ra, rb);
            out[obase + (size_t)(2*u)  *HW + p1] = ra;
            out[obase + (size_t)(2*u+1)*HW + p1] = rb;
        }
    }
}

// ---------------- 6) 2x2 maxpool ----------------
__global__ __launch_bounds__(256)
void k_pool(const float* __restrict__ out, float* __restrict__ down) {
    int idx = blockIdx.x * 256 + threadIdx.x;     // [b][c][h2][w2]
    int w2 = idx & 127;
    int r  = idx >> 7;
    int h2 = r & 127;
    int bc = r >> 7;
    size_t p = (size_t)bc*HW + (size_t)(2*h2)*W + 2*w2;
    float2 a = *(const float2*)(out + p);
    float2 bq = *(const float2*)(out + p + W);
    down[idx] = fmaxf(fmaxf(a.x, a.y), fmaxf(bq.x, bq.y));
}

// ---------------- launch ----------------
extern "C" void kernel_launch(void* const* d_in, const int* in_sizes, int n_in,
                              void* d_out, int out_size) {
    const float* x       = (const float*)d_in[0];
    const float* hconv_w = (const float*)d_in[1];
    const float* hconv_b = (const float*)d_in[2];
    const float* vconv_w = (const float*)d_in[3];
    const float* vconv_b = (const float*)d_in[4];
    const float* pw_w    = (const float*)d_in[5];
    const float* pw_b    = (const float*)d_in[6];
    const float* bn_w    = (const float*)d_in[7];
    const float* bn_b    = (const float*)d_in[8];
    const float* q_w     = (const float*)d_in[9];
    const float* q_b     = (const float*)d_in[10];
    const float* k_w     = (const float*)d_in[11];
    const float* k_b     = (const float*)d_in[12];
    const float* v_w     = (const float*)d_in[13];
    const float* v_b     = (const float*)d_in[14];
    const float* gamma   = (const float*)d_in[15];
    float* out = (float*)d_out;

    const int ATTN_SMEM = (4352 + 256*68) * 4;           // 87040 B
    const int QKV_SMEM  = (C*80 + 256*68) * 4;           // 90112 B
    const int CONV_SMEM = (256*68) * 4;                  // 69632 B
    static bool attr_done = false;
    if (!attr_done) {
        cudaFuncSetAttribute(k_attn,    cudaFuncAttributeMaxDynamicSharedMemorySize, ATTN_SMEM);
        cudaFuncSetAttribute(k_qkv,     cudaFuncAttributeMaxDynamicSharedMemorySize, QKV_SMEM);
        cudaFuncSetAttribute(k_conv_pw, cudaFuncAttributeMaxDynamicSharedMemorySize, CONV_SMEM);
        attr_done = true;
    }

    k_zero<<<1, 256>>>();
    k_conv_pw<<<BB*H, 256, CONV_SMEM>>>(x, hconv_w, hconv_b, vconv_w, vconv_b, pw_w, pw_b);
    k_prep<<<1, 256>>>(bn_w, bn_b, q_w, q_b, k_w, k_b, v_w, v_b);
    k_qkv<<<BB*H, 256, QKV_SMEM>>>();
    k_attn<<<BB*256, 128, ATTN_SMEM>>>(1, nullptr, gamma);   // height pass
    k_attn<<<BB*256, 128, ATTN_SMEM>>>(0, out, gamma);       // width pass + epilogue
    k_pool<<<(TOT/4)/256, 256>>>(out, out + TOT);
}

// round 17
// speedup vs baseline: 1.6602x; 1.6602x over previous
#include <cuda_runtime.h>
#include <math.h>

#define BB 4
#define C 64
#define CQn 8
#define H 256
#define W 256
#define HW 65536
#define CHW (C*HW)          // 4194304
#define TOT (BB*CHW)        // 16777216

typedef unsigned long long u64;

// ---- packed f32x2 helpers ----
__device__ __forceinline__ u64 pk2(float a, float b) {
    u64 r;
    asm("mov.b64 %0, {%1, %2};" : "=l"(r) : "r"(__float_as_uint(a)), "r"(__float_as_uint(b)));
    return r;
}
__device__ __forceinline__ void upk2(u64 v, float& a, float& b) {
    unsigned lo, hi;
    asm("mov.b64 {%0, %1}, %2;" : "=r"(lo), "=r"(hi) : "l"(v));
    a = __uint_as_float(lo); b = __uint_as_float(hi);
}
__device__ __forceinline__ u64 fma2(u64 a, u64 b, u64 c) {
    u64 d;
    asm("fma.rn.f32x2 %0, %1, %2, %3;" : "=l"(d) : "l"(a), "l"(b), "l"(c));
    return d;
}
__device__ __forceinline__ u64 add2(u64 a, u64 b) {
    u64 d;
    asm("add.rn.f32x2 %0, %1, %2;" : "=l"(d) : "l"(a), "l"(b));
    return d;
}

// ---------------- scratch ----------------
__device__ float g_y0[TOT];                 // pre-norm pointwise output (NCHW)
__device__ float g_val[TOT];                // v projection (channels-last [b][h][w][c])
__device__ float g_att[TOT];                // h_out (channels-last [b][i][w][c])
__device__ float g_q[BB*HW*CQn];            // channels-last [b][h][w][8]
__device__ float g_k[BB*HW*CQn];
__device__ float g_isum[BB*C], g_isq[BB*C];
__device__ float g_alpha[BB*C], g_beta[BB*C];
__device__ float g_wT[BB*C*80];             // folded qkv weights [b][c][80]
__device__ float g_bf[BB*80];               // folded qkv biases  [b][80]

// ---------------- 0) zero the stat accumulators ----------------
__global__ void k_zero() {
    int t = threadIdx.x;
    if (t < BB*C) { g_isum[t] = 0.f; g_isq[t] = 0.f; }
}

// ---------------- 1) axial conv + relu + pointwise + fused instance stats ----------------
__global__ __launch_bounds__(256, 2)
void k_conv_pw(const float* __restrict__ x,
               const float* __restrict__ hw_, const float* __restrict__ hb,
               const float* __restrict__ vw_, const float* __restrict__ vb,
               const float* __restrict__ pww, const float* __restrict__ pwb) {
    extern __shared__ float s_stage[];      // 256 x 68
    __shared__ float s_hw[C*5], s_vw[C*5], s_hb[C], s_vb[C];
    __shared__ float s_pwT[C*C];            // [c][o] transposed
    __shared__ u64   s_pwb2[C/2];
    int tid = threadIdx.x;
    for (int i = tid; i < C*5; i += 256) { s_hw[i] = hw_[i]; s_vw[i] = vw_[i]; }
    for (int i = tid; i < C;   i += 256) { s_hb[i] = hb[i]; s_vb[i] = vb[i]; }
    for (int i = tid; i < C*C; i += 256) { int o = i >> 6, c = i & 63; s_pwT[c*C + o] = pww[i]; }
    if (tid < C/2) s_pwb2[tid] = pk2(pwb[2*tid], pwb[2*tid+1]);
    __syncthreads();

    int row = blockIdx.x;
    int b = row >> 8, h = row & 255;
    int w = tid;
    const float* xb = x + (size_t)b * CHW;

    u64 acc[C/2];
    #pragma unroll
    for (int o = 0; o < C/2; o++) acc[o] = s_pwb2[o];

    bool wok[5], hok[5];
    #pragma unroll
    for (int t = 0; t < 5; t++) {
        int ww = w + t - 2; wok[t] = (ww >= 0 && ww < W);
        int hh = h + t - 2; hok[t] = (hh >= 0 && hh < H);
    }

    float xh_a[5], xv_a[5], xh_b[5], xv_b[5];
    {
        const float* xc = xb + h * W;
        #pragma unroll
        for (int t = 0; t < 5; t++) {
            xh_a[t] = wok[t] ? xc[w + t - 2] : 0.f;
            xv_a[t] = hok[t] ? xb[(h + t - 2)*W + w] : 0.f;
        }
    }
    #pragma unroll 4
    for (int c = 0; c < C; c++) {
        float* xh = (c & 1) ? xh_b : xh_a;
        float* xv = (c & 1) ? xv_b : xv_a;
        float* nh = (c & 1) ? xh_a : xh_b;
        float* nv = (c & 1) ? xv_a : xv_b;
        if (c < C-1) {
            const float* xc1 = xb + (c+1) * HW + h * W;
            #pragma unroll
            for (int t = 0; t < 5; t++) {
                nh[t] = wok[t] ? xc1[w + t - 2] : 0.f;
                nv[t] = hok[t] ? xb[(c+1)*HW + (h + t - 2)*W + w] : 0.f;
            }
        }
        float hs = s_hb[c], vs = s_vb[c];
        #pragma unroll
        for (int t = 0; t < 5; t++) {
            hs = fmaf(s_hw[c*5 + t], xh[t], hs);
            vs = fmaf(s_vw[c*5 + t], xv[t], vs);
        }
        float a = hs + vs + xh[2];
        a = a > 0.f ? a : 0.f;
        u64 a2 = pk2(a, a);
        const ulonglong2* wr = (const ulonglong2*)(s_pwT + c*C);
        #pragma unroll
        for (int o = 0; o < C/4; o++) {
            ulonglong2 ww = wr[o];
            acc[2*o]   = fma2(a2, ww.x, acc[2*o]);
            acc[2*o+1] = fma2(a2, ww.y, acc[2*o+1]);
        }
    }
    size_t base = (size_t)b * CHW + h * W + w;
    #pragma unroll
    for (int o = 0; o < C/2; o++) {
        float a, bb; upk2(acc[o], a, bb);
        g_y0[base + (size_t)(2*o)   * HW] = a;
        g_y0[base + (size_t)(2*o+1) * HW] = bb;
        s_stage[tid*68 + 2*o]     = a;
        s_stage[tid*68 + 2*o + 1] = bb;
    }
    __syncthreads();
    {
        int ch = tid & 63, pb = tid >> 6;
        float s = 0.f, qq = 0.f;
        #pragma unroll 8
        for (int p = pb*64; p < pb*64 + 64; p++) {
            float v = s_stage[p*68 + ch];
            s += v; qq = fmaf(v, v, qq);
        }
        atomicAdd(&g_isum[b*C + ch], s);
        atomicAdd(&g_isq [b*C + ch], qq);
    }
}

// ---------------- 3) alpha/beta + folded qkv weights/biases ----------------
__global__ __launch_bounds__(256)
void k_prep(const float* __restrict__ bn_w, const float* __restrict__ bn_b,
            const float* __restrict__ qw, const float* __restrict__ qb,
            const float* __restrict__ kw, const float* __restrict__ kb,
            const float* __restrict__ vw, const float* __restrict__ vb) {
    __shared__ float s_al[BB*C], s_be[BB*C];
    int tid = threadIdx.x;
    if (tid < C) {
        int c = tid;
        const float EPS = 1e-5f, R = 0.7f, R1 = 0.3f;
        float im[BB], iv[BB];
        float bm = 0.f, ey2 = 0.f;
        for (int b = 0; b < BB; b++) {
            float s  = g_isum[b*C + c] * (1.0f/HW);
            float sq = g_isq [b*C + c] * (1.0f/HW);
            im[b] = s; iv[b] = sq - s*s;
            bm += s; ey2 += sq;
        }
        bm *= 0.25f; ey2 *= 0.25f;
        float bv = ey2 - bm*bm;
        float rB = rsqrtf(bv + EPS);
        float wv = bn_w[c], bb = bn_b[c];
        for (int b = 0; b < BB; b++) {
            float rI = rsqrtf(iv[b] + EPS);
            float al = R*rI + R1*rB*wv;
            float be = -R*im[b]*rI + R1*(bb - bm*rB*wv);
            g_alpha[b*C + c] = al; g_beta[b*C + c] = be;
            s_al[b*C + c] = al;    s_be[b*C + c] = be;
        }
    }
    __syncthreads();
    for (int idx = tid; idx < BB*C*80; idx += 256) {
        int b = idx / (C*80);
        int r = idx % (C*80);
        int c = r / 80, o = r % 80;
        float wv = (o < 8) ? qw[o*C + c] : (o < 16) ? kw[(o-8)*C + c] : vw[(o-16)*C + c];
        g_wT[idx] = wv * s_al[b*C + c];
    }
    for (int t = tid; t < BB*80; t += 256) {
        int b = t / 80, o = t % 80;
        float s = (o < 8) ? qb[o] : (o < 16) ? kb[o-8] : vb[o-16];
        const float* wrow = (o < 8) ? (qw + o*C) : (o < 16) ? (kw + (o-8)*C) : (vw + (o-16)*C);
        #pragma unroll 8
        for (int c = 0; c < C; c++) s = fmaf(wrow[c], s_be[b*C + c], s);
        g_bf[t] = s;
    }
}

// ---------------- 4) q/k/v projections (folded, double-buffered prefetch) ----------------
__global__ __launch_bounds__(256, 2)
void k_qkv() {
    extern __shared__ float sm[];
    float* s_wT    = sm;                    // 64 x 80 (folded, this batch)
    float* s_stage = sm + C*80;             // 256 x 68 (padded)
    __shared__ u64 s_b2[40];
    int tid = threadIdx.x;
    int b = blockIdx.x >> 8, h = blockIdx.x & 255;

    for (int i = tid; i < C*80; i += 256) s_wT[i] = g_wT[b*C*80 + i];
    if (tid < 40) s_b2[tid] = pk2(g_bf[b*80 + 2*tid], g_bf[b*80 + 2*tid + 1]);
    __syncthreads();

    u64 acc[40];
    #pragma unroll
    for (int o = 0; o < 40; o++) acc[o] = s_b2[o];

    size_t ybase = (size_t)b * CHW + h * W + tid;
    float ya[16], yb[16];
    #pragma unroll
    for (int u = 0; u < 16; u++) ya[u] = g_y0[ybase + (size_t)u * HW];
    #pragma unroll
    for (int cb = 0; cb < 4; cb++) {
        float* ycur = (cb & 1) ? yb : ya;
        float* ynxt = (cb & 1) ? ya : yb;
        if (cb < 3) {
            #pragma unroll
            for (int u = 0; u < 16; u++)
                ynxt[u] = g_y0[ybase + (size_t)(16*(cb+1) + u) * HW];
        }
        #pragma unroll
        for (int u = 0; u < 16; u++) {
            int c = cb*16 + u;
            u64 y2 = pk2(ycur[u], ycur[u]);
            const ulonglong2* wr = (const ulonglong2*)(s_wT + c*80);
            #pragma unroll
            for (int o = 0; o < 20; o++) {
                ulonglong2 ww = wr[o];
                acc[2*o]   = fma2(y2, ww.x, acc[2*o]);
                acc[2*o+1] = fma2(y2, ww.y, acc[2*o+1]);
            }
        }
    }

    size_t pq = ((size_t)b*HW + h*W + tid) * 8;
    {
        float a0,a1,a2,a3;
        upk2(acc[0], a0, a1); upk2(acc[1], a2, a3);
        *(float4*)(g_q + pq) = make_float4(a0,a1,a2,a3);
        upk2(acc[2], a0, a1); upk2(acc[3], a2, a3);
        *(float4*)(g_q + pq + 4) = make_float4(a0,a1,a2,a3);
        upk2(acc[4], a0, a1); upk2(acc[5], a2, a3);
        *(float4*)(g_k + pq) = make_float4(a0,a1,a2,a3);
        upk2(acc[6], a0, a1); upk2(acc[7], a2, a3);
        *(float4*)(g_k + pq + 4) = make_float4(a0,a1,a2,a3);
    }
    #pragma unroll
    for (int u = 0; u < 32; u++) {
        float a, bb; upk2(acc[8 + u], a, bb);
        s_stage[tid*68 + 2*u]     = a;
        s_stage[tid*68 + 2*u + 1] = bb;
    }
    __syncthreads();
    float4* gv = (float4*)(g_val + ((size_t)b*HW + h*W) * 64);
    for (int e = tid; e < 4096; e += 256) {
        int p = e >> 4, c4 = e & 15;
        gv[e] = *(float4*)(s_stage + p*68 + c4*4);
    }
}

// ---------------- 5) criss-cross attention: 128 threads, 2 px/thread, tiled weights ----
__global__ __launch_bounds__(128)
void k_attn(int height, float* __restrict__ out, const float* __restrict__ gamma) {
    extern __shared__ float sm[];
    float* q_s = sm;            // 256 x 8
    float* k_s = sm + 2048;     // 256 x 8
    float* z_s = sm + 4096;     // 256 (invz)
    float* v_s = sm + 4352;     // 256 x 68 (padded)
    int tid = threadIdx.x;
    int b = blockIdx.x >> 8;
    int f = blockIdx.x & 255;
    int p0 = tid, p1 = tid + 128;

    const float4* gq = (const float4*)(g_q   + (size_t)b*HW*8);
    const float4* gk = (const float4*)(g_k   + (size_t)b*HW*8);
    const float4* gv = (const float4*)(g_val + (size_t)b*HW*64);

    if (height) {
        for (int e = tid; e < 512; e += 128) {
            int j = e >> 1, c4 = e & 1;
            size_t g = ((size_t)j*W + f)*2 + c4;
            ((float4*)q_s)[e] = gq[g];
            ((float4*)k_s)[e] = gk[g];
        }
        for (int e = tid; e < 4096; e += 128) {
            int j = e >> 4, c4 = e & 15;
            *(float4*)(v_s + j*68 + c4*4) = gv[((size_t)j*W + f)*16 + c4];
        }
    } else {
        size_t pb = (size_t)f * W;
        for (int e = tid; e < 512; e += 128) {
            ((float4*)q_s)[e] = gq[pb*2 + e];
            ((float4*)k_s)[e] = gk[pb*2 + e];
        }
        for (int e = tid; e < 4096; e += 128) {
            int j = e >> 4, c4 = e & 15;
            *(float4*)(v_s + j*68 + c4*4) = gv[pb*16 + e];
        }
    }
    __syncthreads();

    const u64 zero2 = pk2(0.f, 0.f);

    u64 k0r[4], k1r[4];
    {
        const ulonglong2* kp0 = (const ulonglong2*)(k_s + p0*8);
        const ulonglong2* kp1 = (const ulonglong2*)(k_s + p1*8);
        ulonglong2 t;
        t = kp0[0]; k0r[0] = t.x; k0r[1] = t.y;
        t = kp0[1]; k0r[2] = t.x; k0r[3] = t.y;
        t = kp1[0]; k1r[0] = t.x; k1r[1] = t.y;
        t = kp1[1]; k1r[2] = t.x; k1r[3] = t.y;
    }

    // ---- pass 1 (thread = sources p0,p1): Z_j = sum_i exp(q_j . k_i) ----
    {
        u64 q0r[4], q1r[4];
        const ulonglong2* qp0 = (const ulonglong2*)(q_s + p0*8);
        const ulonglong2* qp1 = (const ulonglong2*)(q_s + p1*8);
        ulonglong2 t;
        t = qp0[0]; q0r[0] = t.x; q0r[1] = t.y;
        t = qp0[1]; q0r[2] = t.x; q0r[3] = t.y;
        t = qp1[0]; q1r[0] = t.x; q1r[1] = t.y;
        t = qp1[1]; q1r[2] = t.x; q1r[3] = t.y;
        float z0 = 0.f, z1 = 0.f;
        for (int i = 0; i < 256; i++) {
            const ulonglong2* kp = (const ulonglong2*)(k_s + i*8);   // broadcast
            ulonglong2 k01 = kp[0], k23 = kp[1];
            u64 a0 = fma2(q0r[1], k01.y, fma2(q0r[0], k01.x, zero2));
            u64 a1 = fma2(q0r[3], k23.y, fma2(q0r[2], k23.x, zero2));
            float sx, sy; upk2(add2(a0, a1), sx, sy);
            z0 += __expf(sx + sy);
            u64 b0 = fma2(q1r[1], k01.y, fma2(q1r[0], k01.x, zero2));
            u64 b1 = fma2(q1r[3], k23.y, fma2(q1r[2], k23.x, zero2));
            upk2(add2(b0, b1), sx, sy);
            z1 += __expf(sx + sy);
        }
        z_s[p0] = 1.0f / z0;
        z_s[p1] = 1.0f / z1;
    }
    __syncthreads();

    // ---- pass 2 (thread = outputs p0,p1), 8-wide weight tiles ----
    // phase A: 8 independent score->exp chains; phase B: pure LDS+FFMA2 stream.
    u64 acc0[32], acc1[32];
    #pragma unroll
    for (int u = 0; u < 32; u++) { acc0[u] = zero2; acc1[u] = zero2; }
    for (int jt = 0; jt < 256; jt += 8) {
        float w0[8], w1[8];
        #pragma unroll
        for (int u = 0; u < 8; u++) {
            int j = jt + u;
            const ulonglong2* qp = (const ulonglong2*)(q_s + j*8);   // broadcast
            ulonglong2 q01 = qp[0], q23 = qp[1];
            float izj = z_s[j];
            u64 a0 = fma2(k0r[1], q01.y, fma2(k0r[0], q01.x, zero2));
            u64 a1 = fma2(k0r[3], q23.y, fma2(k0r[2], q23.x, zero2));
            float sx, sy; upk2(add2(a0, a1), sx, sy);
            w0[u] = __expf(sx + sy) * izj;
            u64 b0 = fma2(k1r[1], q01.y, fma2(k1r[0], q01.x, zero2));
            u64 b1 = fma2(k1r[3], q23.y, fma2(k1r[2], q23.x, zero2));
            upk2(add2(b0, b1), sx, sy);
            w1[u] = __expf(sx + sy) * izj;
        }
        #pragma unroll
        for (int u = 0; u < 8; u++) {
            u64 e02 = pk2(w0[u], w0[u]);
            u64 e12 = pk2(w1[u], w1[u]);
            const ulonglong2* vr = (const ulonglong2*)(v_s + (jt+u)*68);  // broadcast
            #pragma unroll
            for (int q = 0; q < 16; q++) {
                ulonglong2 vv = vr[q];
                acc0[2*q]   = fma2(e02, vv.x, acc0[2*q]);
                acc0[2*q+1] = fma2(e02, vv.y, acc0[2*q+1]);
                acc1[2*q]   = fma2(e12, vv.x, acc1[2*q]);
                acc1[2*q+1] = fma2(e12, vv.y, acc1[2*q+1]);
            }
        }
    }

    if (height) {
        __syncthreads();
        #pragma unroll
        for (int u = 0; u < 32; u++) {
            float a, bb;
            upk2(acc0[u], a, bb);
            v_s[p0*68 + 2*u] = a; v_s[p0*68 + 2*u + 1] = bb;
            upk2(acc1[u], a, bb);
            v_s[p1*68 + 2*u] = a; v_s[p1*68 + 2*u + 1] = bb;
        }
        __syncthreads();
        float4* ga = (float4*)(g_att + (size_t)b*HW*64);
        for (int e = tid; e < 4096; e += 128) {
            int j = e >> 4, c4 = e & 15;
            ga[((size_t)j*W + f)*16 + c4] = *(float4*)(v_s + j*68 + c4*4);
        }
    } else {
        __syncthreads();
        u64* s_al2 = (u64*)q_s;           // 32 pairs
        u64* s_be2 = ((u64*)q_s) + 32;
        if (tid < 32) {
            s_al2[tid] = pk2(g_alpha[b*C + 2*tid], g_alpha[b*C + 2*tid + 1]);
            s_be2[tid] = pk2(g_beta [b*C + 2*tid], g_beta [b*C + 2*tid + 1]);
        }
        const float4* ga = (const float4*)(g_att + ((size_t)b*HW + (size_t)f*W) * 64);
        for (int e = tid; e < 4096; e += 128) {
            int p = e >> 4, c4 = e & 15;
            *(float4*)(v_s + p*68 + c4*4) = ga[e];
        }
        __syncthreads();
        float gm = gamma[0];
        u64 gm2 = pk2(gm, gm);
        size_t obase = (size_t)b*CHW + (size_t)f*W;
        const u64* ar0 = (const u64*)(v_s + p0*68);
        const u64* ar1 = (const u64*)(v_s + p1*68);
        #pragma unroll
        for (int u = 0; u < 32; u++) {
            u64 hv0 = add2(ar0[u], acc0[u]);
            u64 y20 = pk2(g_y0[obase + (size_t)(2*u)*HW + p0], g_y0[obase + (size_t)(2*u+1)*HW + p0]);
            u64 r0 = fma2(gm2, hv0, fma2(s_al2[u], y20, s_be2[u]));
            float ra, rb; upk2(r0, ra, rb);
            out[obase + (size_t)(2*u)  *HW + p0] = ra;
            out[obase + (size_t)(2*u+1)*HW + p0] = rb;
            u64 hv1 = add2(ar1[u], acc1[u]);
            u64 y21 = pk2(g_y0[obase + (size_t)(2*u)*HW + p1], g_y0[obase + (size_t)(2*u+1)*HW + p1]);
            u64 r1 = fma2(gm2, hv1, fma2(s_al2[u], y21, s_be2[u]));
            upk2(r1, ra, rb);
            out[obase + (size_t)(2*u)  *HW + p1] = ra;
            out[obase + (size_t)(2*u+1)*HW + p1] = rb;
        }
    }
}

// ---------------- 6) 2x2 maxpool ----------------
__global__ __launch_bounds__(256)
void k_pool(const float* __restrict__ out, float* __restrict__ down) {
    int idx = blockIdx.x * 256 + threadIdx.x;     // [b][c][h2][w2]
    int w2 = idx & 127;
    int r  = idx >> 7;
    int h2 = r & 127;
    int bc = r >> 7;
    size_t p = (size_t)bc*HW + (size_t)(2*h2)*W + 2*w2;
    float2 a = *(const float2*)(out + p);
    float2 bq = *(const float2*)(out + p + W);
    down[idx] = fmaxf(fmaxf(a.x, a.y), fmaxf(bq.x, bq.y));
}

// ---------------- launch ----------------
extern "C" void kernel_launch(void* const* d_in, const int* in_sizes, int n_in,
                              void* d_out, int out_size) {
    const float* x       = (const float*)d_in[0];
    const float* hconv_w = (const float*)d_in[1];
    const float* hconv_b = (const float*)d_in[2];
    const float* vconv_w = (const float*)d_in[3];
    const float* vconv_b = (const float*)d_in[4];
    const float* pw_w    = (const float*)d_in[5];
    const float* pw_b    = (const float*)d_in[6];
    const float* bn_w    = (const float*)d_in[7];
    const float* bn_b    = (const float*)d_in[8];
    const float* q_w     = (const float*)d_in[9];
    const float* q_b     = (const float*)d_in[10];
    const float* k_w     = (const float*)d_in[11];
    const float* k_b     = (const float*)d_in[12];
    const float* v_w     = (const float*)d_in[13];
    const float* v_b     = (const float*)d_in[14];
    const float* gamma   = (const float*)d_in[15];
    float* out = (float*)d_out;

    const int ATTN_SMEM = (4352 + 256*68) * 4;           // 87040 B
    const int QKV_SMEM  = (C*80 + 256*68) * 4;           // 90112 B
    const int CONV_SMEM = (256*68) * 4;                  // 69632 B
    static bool attr_done = false;
    if (!attr_done) {
        cudaFuncSetAttribute(k_attn,    cudaFuncAttributeMaxDynamicSharedMemorySize, ATTN_SMEM);
        cudaFuncSetAttribute(k_qkv,     cudaFuncAttributeMaxDynamicSharedMemorySize, QKV_SMEM);
        cudaFuncSetAttribute(k_conv_pw, cudaFuncAttributeMaxDynamicSharedMemorySize, CONV_SMEM);
        attr_done = true;
    }

    k_zero<<<1, 256>>>();
    k_conv_pw<<<BB*H, 256, CONV_SMEM>>>(x, hconv_w, hconv_b, vconv_w, vconv_b, pw_w, pw_b);
    k_prep<<<1, 256>>>(bn_w, bn_b, q_w, q_b, k_w, k_b, v_w, v_b);
    k_qkv<<<BB*H, 256, QKV_SMEM>>>();
    k_attn<<<BB*256, 128, ATTN_SMEM>>>(1, nullptr, gamma);   // height pass
    k_attn<<<BB*256, 128, ATTN_SMEM>>>(0, out, gamma);       // width pass + epilogue
    k_pool<<<(TOT/4)/256, 256>>>(out, out + TOT);
}